// round 5
// baseline (speedup 1.0000x reference)
#include <cuda_runtime.h>
#include <math.h>
#include <stdint.h>

// Problem constants
#define B_    16
#define C_    1024
#define T_    64
#define N_    12
#define BT_   (B_ * T_)       // 1024 frames
#define NF_   1024
#define ROWS_ (BT_ * N_)      // 12288
#define TN_   (T_ * N_)       // 768
#define NB_   2048            // fused B rows: [MwT | wg^T]

// Scratch (static device globals)
__device__ float g_feat[ROWS_ * NF_];   // feat, RNA-rounded to tf32
__device__ float g_TG[ROWS_ * NB_];     // [tM | G] fused output
__device__ float g_BigB[NB_ * NF_];     // rows 0-1023: MwT, rows 1024-2047: wg^T
__device__ float g_wtr[NF_ * NF_];      // Wtheta rounded
__device__ float g_wpr[NF_ * NF_];      // Wphi rounded
__device__ float g_vtp[NF_];
__device__ float g_vpt[NF_];
__device__ float g_bb[1];

// ---------------------------------------------------------------------------
// Helpers (baseline PTX only — no arch-'a' gated instructions)
// ---------------------------------------------------------------------------
__device__ __forceinline__ float rna_tf32(float x) {
    float r;
    asm("cvt.rna.tf32.f32 %0, %1;" : "=f"(r) : "f"(x));
    return r;
}
__device__ __forceinline__ uint32_t smem_u32(const void* p) {
    uint32_t a;
    asm("{ .reg .u64 t; cvta.to.shared.u64 t, %1; cvt.u32.u64 %0, t; }" : "=r"(a) : "l"(p));
    return a;
}
__device__ __forceinline__ void cp16(uint32_t s, const void* g) {
    asm volatile("cp.async.cg.shared.global [%0], [%1], 16;" :: "r"(s), "l"(g) : "memory");
}
#define CP_COMMIT() asm volatile("cp.async.commit_group;" ::: "memory")
#define SWZ(x) ((x) ^ (((x) >> 3) & 0x70))

__device__ __forceinline__ void ldsm4(uint32_t* r, uint32_t addr) {
    asm volatile("ldmatrix.sync.aligned.m8n8.x4.shared.b16 {%0,%1,%2,%3}, [%4];"
                 : "=r"(r[0]), "=r"(r[1]), "=r"(r[2]), "=r"(r[3]) : "r"(addr));
}
__device__ __forceinline__ void mma_tf32(float* c, const uint32_t* a, uint32_t b0, uint32_t b1) {
    asm volatile("mma.sync.aligned.m16n8k8.row.col.f32.tf32.tf32.f32 "
                 "{%0,%1,%2,%3}, {%4,%5,%6,%7}, {%8,%9}, {%0,%1,%2,%3};"
                 : "+f"(c[0]), "+f"(c[1]), "+f"(c[2]), "+f"(c[3])
                 : "r"(a[0]), "r"(a[1]), "r"(a[2]), "r"(a[3]), "r"(b0), "r"(b1));
}

// ---------------------------------------------------------------------------
// Tensor-core tf32 GEMM: C[m,n] = sum_k A[m,k]*Bm[n,k]; A[M,K], Bm[N,K] row-major.
// Block 256x128, K-chunk 32, 3-stage cp.async, 16 warps (each 64x32).
// ---------------------------------------------------------------------------
#define BM 256
#define BN 128
#define BK 32
#define STAGES 3
#define A_STAGE_BYTES 32768
#define B_STAGE_BYTES 16384
#define GEMM_SMEM (STAGES * (A_STAGE_BYTES + B_STAGE_BYTES))  // 147456

template <bool ROUND>
__global__ void __launch_bounds__(512, 1) mma_gemm(const float* __restrict__ A,
                                                   const float* __restrict__ Bm,
                                                   float* __restrict__ C,
                                                   int K, int ldc) {
    extern __shared__ char smem[];
    const uint32_t sb = smem_u32(smem);
    const int tid = threadIdx.x, lane = tid & 31, wid = tid >> 5;
    const int m0 = blockIdx.y * BM, n0 = blockIdx.x * BN;
    const int warp_m = wid & 3, warp_n = wid >> 2;

    // cp.async tiling: 8 threads x 16B per 128B row, 64 rows per pass (512 thr)
    const int r = tid >> 3;
    const int o16 = (tid & 7) << 4;
    const int c4 = (tid & 7) << 2;

    float acc[4][4][4];
#pragma unroll
    for (int i = 0; i < 4; i++)
#pragma unroll
        for (int j = 0; j < 4; j++)
#pragma unroll
            for (int k = 0; k < 4; k++) acc[i][j][k] = 0.f;

    // ldmatrix per-lane UNSWIZZLED base offsets (swizzle applied per k-step;
    // base has bits 5-6 clear so base + ks*32 never carries pre-swizzle)
    const int lrow = lane & 15;
    const int lcol = (lane >> 4) << 4;
    uint32_t a_base[4], b_base[2];
#pragma unroll
    for (int mt = 0; mt < 4; mt++)
        a_base[mt] = (uint32_t)((warp_m * 64 + mt * 16 + lrow) * 128 + lcol);
#pragma unroll
    for (int nh = 0; nh < 2; nh++)
        b_base[nh] = (uint32_t)((warp_n * 32 + nh * 16 + lrow) * 128 + lcol);

#define LOAD_STAGE(chunk, stage)                                                   \
    do {                                                                           \
        uint32_t sA = sb + (stage) * A_STAGE_BYTES;                                \
        uint32_t sB = sb + STAGES * A_STAGE_BYTES + (stage) * B_STAGE_BYTES;       \
        int k0 = (chunk) * BK;                                                     \
        _Pragma("unroll") for (int t = 0; t < 4; t++) {                            \
            int rr = r + t * 64;                                                   \
            cp16(sA + SWZ((uint32_t)(rr * 128 + o16)),                             \
                 A + (size_t)(m0 + rr) * K + k0 + c4);                             \
        }                                                                          \
        _Pragma("unroll") for (int t = 0; t < 2; t++) {                            \
            int rr = r + t * 64;                                                   \
            cp16(sB + SWZ((uint32_t)(rr * 128 + o16)),                             \
                 Bm + (size_t)(n0 + rr) * K + k0 + c4);                            \
        }                                                                          \
        CP_COMMIT();                                                               \
    } while (0)

    LOAD_STAGE(0, 0);
    LOAD_STAGE(1, 1);

    const int nk = K / BK;
    for (int i = 0; i < nk; i++) {
        const int st = i % STAGES;
        if (i + 2 < nk) {
            asm volatile("cp.async.wait_group 1;" ::: "memory");
            __syncthreads();
            LOAD_STAGE(i + 2, (i + 2) % STAGES);
        } else {
            asm volatile("cp.async.wait_group 0;" ::: "memory");
            __syncthreads();
        }
        const uint32_t sA = sb + st * A_STAGE_BYTES;
        const uint32_t sB = sb + STAGES * A_STAGE_BYTES + st * B_STAGE_BYTES;
#pragma unroll
        for (int ks = 0; ks < 4; ks++) {
            uint32_t a[4][4], b[2][4];
#pragma unroll
            for (int mt = 0; mt < 4; mt++)
                ldsm4(a[mt], sA + SWZ(a_base[mt] + (uint32_t)(ks * 32)));
#pragma unroll
            for (int nh = 0; nh < 2; nh++)
                ldsm4(b[nh], sB + SWZ(b_base[nh] + (uint32_t)(ks * 32)));
#pragma unroll
            for (int mt = 0; mt < 4; mt++)
#pragma unroll
                for (int nt = 0; nt < 4; nt++)
                    mma_tf32(acc[mt][nt], a[mt], b[nt >> 1][nt & 1], b[nt >> 1][(nt & 1) + 2]);
        }
    }
#undef LOAD_STAGE

    // Epilogue: direct float2 stores
    const int mrow = lane >> 2;
    const int mcol = (lane & 3) << 1;
#pragma unroll
    for (int mt = 0; mt < 4; mt++) {
#pragma unroll
        for (int nt = 0; nt < 4; nt++) {
            int row = m0 + warp_m * 64 + mt * 16 + mrow;
            int col = n0 + warp_n * 32 + nt * 8 + mcol;
            float2 v0 = make_float2(acc[mt][nt][0], acc[mt][nt][1]);
            float2 v1 = make_float2(acc[mt][nt][2], acc[mt][nt][3]);
            if (ROUND) {
                v0.x = rna_tf32(v0.x); v0.y = rna_tf32(v0.y);
                v1.x = rna_tf32(v1.x); v1.y = rna_tf32(v1.y);
            }
            *(float2*)&C[(size_t)row * ldc + col] = v0;
            *(float2*)&C[(size_t)(row + 8) * ldc + col] = v1;
        }
    }
}

// ---------------------------------------------------------------------------
// Transpose x[B,C,T,N] -> feat[(b*T+t)*N+n, c], RNA-rounded to tf32
// ---------------------------------------------------------------------------
__global__ void transpose_x(const float* __restrict__ x) {
    __shared__ float tile[32][33];
    const int b = blockIdx.z;
    const int c0 = blockIdx.y * 32;
    const int tn0 = blockIdx.x * 32;
    const int tx = threadIdx.x, ty = threadIdx.y;
    const float* xp = x + ((size_t)b * C_ + c0) * TN_ + tn0;
#pragma unroll
    for (int i = 0; i < 32; i += 8)
        tile[ty + i][tx] = xp[(size_t)(ty + i) * TN_ + tx];
    __syncthreads();
    float* fp = g_feat + ((size_t)b * TN_ + tn0) * NF_ + c0;
#pragma unroll
    for (int i = 0; i < 32; i += 8)
        fp[(size_t)(ty + i) * NF_ + tx] = rna_tf32(tile[tx][ty + i]);
}

// w_gcn [K,N] -> g_BigB rows 1024..2047 ([N,K]), rounded
__global__ void transpose_wg(const float* __restrict__ w) {
    __shared__ float tile[32][33];
    const int k0 = blockIdx.y * 32;
    const int n0 = blockIdx.x * 32;
    const int tx = threadIdx.x, ty = threadIdx.y;
#pragma unroll
    for (int i = 0; i < 32; i += 8)
        tile[ty + i][tx] = w[(size_t)(k0 + ty + i) * NF_ + n0 + tx];
    __syncthreads();
    float* dst = g_BigB + (size_t)NF_ * NF_;
#pragma unroll
    for (int i = 0; i < 32; i += 8)
        dst[(size_t)(n0 + ty + i) * NF_ + k0 + tx] = rna_tf32(tile[tx][ty + i]);
}

__global__ void round_copy(const float4* __restrict__ in, float4* __restrict__ out) {
    const int i = blockIdx.x * blockDim.x + threadIdx.x;
    float4 v = in[i];
    v.x = rna_tf32(v.x); v.y = rna_tf32(v.y);
    v.z = rna_tf32(v.z); v.w = rna_tf32(v.w);
    out[i] = v;
}

// ---------------------------------------------------------------------------
// Bias cross-term vectors (exact fp32)
// ---------------------------------------------------------------------------
__global__ void bias_vecs(const float* __restrict__ wt, const float* __restrict__ bt,
                          const float* __restrict__ wp, const float* __restrict__ bp) {
    const int c = blockIdx.x * blockDim.x + threadIdx.x;
    if (c < NF_) {
        float a = 0.f, b2 = 0.f;
        const float* wtr = wt + (size_t)c * NF_;
        const float* wpr = wp + (size_t)c * NF_;
        for (int r = 0; r < NF_; ++r) {
            a += wtr[r] * bp[r];
            b2 += wpr[r] * bt[r];
        }
        g_vtp[c] = a;
        g_vpt[c] = b2;
    }
    if (blockIdx.x == 0 && threadIdx.x == 0) {
        float s = 0.f;
        for (int r = 0; r < NF_; ++r) s += bt[r] * bp[r];
        g_bb[0] = s;
    }
}

// ---------------------------------------------------------------------------
__device__ __forceinline__ float blockSum512(float v, float* red) {
    const int lane = threadIdx.x & 31, warp = threadIdx.x >> 5;
#pragma unroll
    for (int o = 16; o > 0; o >>= 1) v += __shfl_xor_sync(0xffffffffu, v, o);
    if (lane == 0) red[warp] = v;
    __syncthreads();
    if (threadIdx.x == 0) {
        float s = 0.f;
        for (int i = 0; i < 16; i++) s += red[i];
        red[16] = s;
    }
    __syncthreads();
    float r = red[16];
    __syncthreads();
    return r;
}

__global__ void __launch_bounds__(512) frame_kernel(const float* __restrict__ Abox,
                                                    const float* __restrict__ ln_w,
                                                    const float* __restrict__ ln_b,
                                                    float* __restrict__ out,
                                                    float* __restrict__ rg_out) {
    const int f = blockIdx.x;
    const int tid = threadIdx.x;
    const int lane = tid & 31, warp = tid >> 5;

    __shared__ float px[12], py[12], sqs[12];
    __shared__ float s_u[12], s_v[12];
    __shared__ float s_rg[12][12];
    __shared__ float red[17];

    if (tid < 12) {
        const float* bx = Abox + ((size_t)f * 12 + tid) * 4;
        float cx = (bx[0] + bx[2]) * 0.5f;
        float cy = (bx[1] + bx[3]) * 0.5f;
        px[tid] = cx; py[tid] = cy; sqs[tid] = cx * cx + cy * cy;
    }

    if (warp < 12) {
        const float* frow = g_feat + ((size_t)f * 12 + warp) * NF_;
        float ua = 0.f, va = 0.f;
#pragma unroll
        for (int k = 0; k < 32; k++) {
            float fv = frow[lane + 32 * k];
            ua += fv * g_vtp[lane + 32 * k];
            va += fv * g_vpt[lane + 32 * k];
        }
#pragma unroll
        for (int o = 16; o > 0; o >>= 1) {
            ua += __shfl_xor_sync(0xffffffffu, ua, o);
            va += __shfl_xor_sync(0xffffffffu, va, o);
        }
        if (lane == 0) { s_u[warp] = ua; s_v[warp] = va; }
    }
    __syncthreads();

    if (warp < 12) {
        const int n = warp;
        const float* tMrow = g_TG + ((size_t)f * 12 + n) * NB_;
        float tr[32];
#pragma unroll
        for (int k = 0; k < 32; k++) tr[k] = tMrow[lane + 32 * k];
        float lg[12];
#pragma unroll
        for (int m = 0; m < 12; m++) {
            const float* fm = g_feat + ((size_t)f * 12 + m) * NF_;
            float a = 0.f;
#pragma unroll
            for (int k = 0; k < 32; k++) a += tr[k] * fm[lane + 32 * k];
#pragma unroll
            for (int o = 16; o > 0; o >>= 1) a += __shfl_xor_sync(0xffffffffu, a, o);
            lg[m] = a;
        }
        if (lane == 0) {
            const float bb = g_bb[0];
            const float scale = 0.03125f;
            float e[12];
            bool msk[12];
            float mx = -INFINITY;
#pragma unroll
            for (int m = 0; m < 12; m++) {
                float d2 = sqs[n] - 2.f * (px[n] * px[m] + py[n] * py[m]) + sqs[m];
                d2 = fmaxf(d2, 0.f);
                float dist = sqrtf(d2);
                msk[m] = (dist > 0.4f);
                float v = (lg[m] + s_u[n] + s_v[m] + bb) * scale;
                e[m] = v;
                if (!msk[m]) mx = fmaxf(mx, v);
            }
            float se = 0.f;
#pragma unroll
            for (int m = 0; m < 12; m++) {
                float ev = msk[m] ? 0.f : expf(e[m] - mx);
                e[m] = ev;
                se += ev;
            }
            float inv = 1.f / se;
#pragma unroll
            for (int m = 0; m < 12; m++) {
                float r = e[m] * inv;
                s_rg[n][m] = r;
                if (rg_out) rg_out[((size_t)f * 12 + n) * 12 + m] = r;
            }
        }
    }
    __syncthreads();

    float aggv[2][12];
#pragma unroll
    for (int cc = 0; cc < 2; cc++) {
        const int c = tid + cc * 512;
        float g[12];
#pragma unroll
        for (int m = 0; m < 12; m++)
            g[m] = g_TG[((size_t)f * 12 + m) * NB_ + NF_ + c];
#pragma unroll
        for (int n = 0; n < 12; n++) {
            float a = 0.f;
#pragma unroll
            for (int m = 0; m < 12; m++) a += s_rg[n][m] * g[m];
            aggv[cc][n] = a;
        }
    }
    float lsum = 0.f;
#pragma unroll
    for (int cc = 0; cc < 2; cc++)
#pragma unroll
        for (int n = 0; n < 12; n++) lsum += aggv[cc][n];
    const float mu = blockSum512(lsum, red) * (1.f / 12288.f);

    float lsq = 0.f;
#pragma unroll
    for (int cc = 0; cc < 2; cc++)
#pragma unroll
        for (int n = 0; n < 12; n++) {
            float d = aggv[cc][n] - mu;
            lsq += d * d;
        }
    const float var = blockSum512(lsq, red) * (1.f / 12288.f);
    const float rstd = rsqrtf(var + 1e-5f);

#pragma unroll
    for (int cc = 0; cc < 2; cc++) {
        const int c = tid + cc * 512;
#pragma unroll
        for (int n = 0; n < 12; n++) {
            float y = (aggv[cc][n] - mu) * rstd * ln_w[n * NF_ + c] + ln_b[n * NF_ + c];
            out[((size_t)f * 12 + n) * NF_ + c] = fmaxf(y, 0.f);
        }
    }
}

// ---------------------------------------------------------------------------
extern "C" void kernel_launch(void* const* d_in, const int* in_sizes, int n_in,
                              void* d_out, int out_size) {
    const float* x  = (const float*)d_in[0];
    const float* A  = (const float*)d_in[1];
    const float* wt = (const float*)d_in[2];
    const float* bt = (const float*)d_in[3];
    const float* wp = (const float*)d_in[4];
    const float* bp = (const float*)d_in[5];
    const float* wg = (const float*)d_in[6];
    const float* lw = (const float*)d_in[7];
    const float* lb = (const float*)d_in[8];

    float* out = (float*)d_out;
    float* rg = (out_size >= (int)(ROWS_ * NF_ + BT_ * N_ * N_))
                    ? out + (size_t)ROWS_ * NF_
                    : nullptr;

    float *feat, *TG, *BigB, *wtr, *wpr;
    cudaGetSymbolAddress((void**)&feat, g_feat);
    cudaGetSymbolAddress((void**)&TG, g_TG);
    cudaGetSymbolAddress((void**)&BigB, g_BigB);
    cudaGetSymbolAddress((void**)&wtr, g_wtr);
    cudaGetSymbolAddress((void**)&wpr, g_wpr);

    cudaFuncSetAttribute(mma_gemm<true>,
                         cudaFuncAttributeMaxDynamicSharedMemorySize, GEMM_SMEM);
    cudaFuncSetAttribute(mma_gemm<false>,
                         cudaFuncAttributeMaxDynamicSharedMemorySize, GEMM_SMEM);

    // Launch order arranged so the big GEMM is launch #6 (ncu -s 5 -c 1 captures it)
    transpose_x<<<dim3(TN_ / 32, C_ / 32, B_), dim3(32, 8)>>>(x);            // 1
    round_copy<<<1024, 256>>>((const float4*)wt, (float4*)wtr);              // 2
    round_copy<<<1024, 256>>>((const float4*)wp, (float4*)wpr);              // 3
    transpose_wg<<<dim3(32, 32), dim3(32, 8)>>>(wg);                         // 4

    // MwT[n,k] = sum_r wphi[n,r]*wtheta[k,r]  -> BigB rows 0..1023 (rounded)
    mma_gemm<true><<<dim3(NF_ / BN, NF_ / BM), 512, GEMM_SMEM>>>(            // 5
        wpr, wtr, BigB, NF_, NF_);
    // [tM | G] = feat @ [MwT | wg^T]^T   (fused, N = 2048)
    mma_gemm<false><<<dim3(NB_ / BN, ROWS_ / BM), 512, GEMM_SMEM>>>(         // 6
        feat, BigB, TG, NF_, NB_);

    bias_vecs<<<NF_ / 128, 128>>>(wt, bt, wp, bp);                           // 7
    frame_kernel<<<BT_, 512>>>(A, lw, lb, out, rg);                          // 8
}

// round 6
// speedup vs baseline: 1.4844x; 1.4844x over previous
#include <cuda_runtime.h>
#include <math.h>
#include <stdint.h>

// Problem constants
#define B_    16
#define C_    1024
#define T_    64
#define N_    12
#define BT_   (B_ * T_)       // 1024 frames
#define NF_   1024
#define ROWS_ (BT_ * N_)      // 12288
#define TN_   (T_ * N_)       // 768
#define NB_   2048            // fused B rows: [MwT | wg^T]

// Scratch (static device globals)
__device__ float g_feat[ROWS_ * NF_];   // feat, RNA-rounded to tf32
__device__ float g_TG[ROWS_ * NB_];     // [tM | G] fused output
__device__ float g_BigB[NB_ * NF_];     // rows 0-1023: MwT, rows 1024-2047: wg^T
__device__ float g_wtr[NF_ * NF_];      // Wtheta rounded
__device__ float g_wpr[NF_ * NF_];      // Wphi rounded
__device__ float g_vtp[NF_];
__device__ float g_vpt[NF_];
__device__ float g_bb[1];

// ---------------------------------------------------------------------------
// Helpers (baseline PTX only — no arch-'a' gated instructions)
// ---------------------------------------------------------------------------
__device__ __forceinline__ float rna_tf32(float x) {
    float r;
    asm("cvt.rna.tf32.f32 %0, %1;" : "=f"(r) : "f"(x));
    return r;
}
__device__ __forceinline__ uint32_t smem_u32(const void* p) {
    uint32_t a;
    asm("{ .reg .u64 t; cvta.to.shared.u64 t, %1; cvt.u32.u64 %0, t; }" : "=r"(a) : "l"(p));
    return a;
}
__device__ __forceinline__ void cp16(uint32_t s, const void* g) {
    asm volatile("cp.async.cg.shared.global [%0], [%1], 16;" :: "r"(s), "l"(g) : "memory");
}
#define CP_COMMIT() asm volatile("cp.async.commit_group;" ::: "memory")
#define SWZ(x) ((x) ^ (((x) >> 3) & 0x70))

__device__ __forceinline__ void ldsm4(uint32_t* r, uint32_t addr) {
    asm volatile("ldmatrix.sync.aligned.m8n8.x4.shared.b16 {%0,%1,%2,%3}, [%4];"
                 : "=r"(r[0]), "=r"(r[1]), "=r"(r[2]), "=r"(r[3]) : "r"(addr));
}
__device__ __forceinline__ void mma_tf32(float* c, const uint32_t* a, uint32_t b0, uint32_t b1) {
    asm volatile("mma.sync.aligned.m16n8k8.row.col.f32.tf32.tf32.f32 "
                 "{%0,%1,%2,%3}, {%4,%5,%6,%7}, {%8,%9}, {%0,%1,%2,%3};"
                 : "+f"(c[0]), "+f"(c[1]), "+f"(c[2]), "+f"(c[3])
                 : "r"(a[0]), "r"(a[1]), "r"(a[2]), "r"(a[3]), "r"(b0), "r"(b1));
}

// ---------------------------------------------------------------------------
// Tensor-core tf32 GEMM: C[m,n] = sum_k A[m,k]*Bm[n,k]; A[M,K], Bm[N,K] row-major.
// Block 128x128, K-chunk 32, 3-stage cp.async, 8 warps (each 64x32), 2 CTA/SM.
// ---------------------------------------------------------------------------
#define BM 128
#define BN 128
#define BK 32
#define STAGES 3
#define STAGE_BYTES 16384
#define GEMM_SMEM (STAGES * 2 * STAGE_BYTES)  // 98304

template <bool ROUND>
__global__ void __launch_bounds__(256, 2) mma_gemm(const float* __restrict__ A,
                                                   const float* __restrict__ Bm,
                                                   float* __restrict__ C,
                                                   int K, int ldc) {
    extern __shared__ char smem[];
    const uint32_t sb = smem_u32(smem);
    const int tid = threadIdx.x, lane = tid & 31, wid = tid >> 5;
    const int m0 = blockIdx.y * BM, n0 = blockIdx.x * BN;
    const int warp_m = wid & 1, warp_n = wid >> 1;

    // cp.async tiling: 8 threads x 16B per 128B row, 32 rows per pass
    const int r = tid >> 3;
    const int o16 = (tid & 7) << 4;
    const int c4 = (tid & 7) << 2;

    float acc[4][4][4];
#pragma unroll
    for (int i = 0; i < 4; i++)
#pragma unroll
        for (int j = 0; j < 4; j++)
#pragma unroll
            for (int k = 0; k < 4; k++) acc[i][j][k] = 0.f;

    // ldmatrix per-lane UNSWIZZLED base offsets (swizzle applied per k-step;
    // base has bits 5-6 clear so base + ks*32 never carries pre-swizzle)
    const int lrow = lane & 15;
    const int lcol = (lane >> 4) << 4;
    uint32_t a_base[4], b_base[2];
#pragma unroll
    for (int mt = 0; mt < 4; mt++)
        a_base[mt] = (uint32_t)((warp_m * 64 + mt * 16 + lrow) * 128 + lcol);
#pragma unroll
    for (int nh = 0; nh < 2; nh++)
        b_base[nh] = (uint32_t)((warp_n * 32 + nh * 16 + lrow) * 128 + lcol);

#define LOAD_STAGE(chunk, stage)                                                   \
    do {                                                                           \
        uint32_t sA = sb + (stage) * STAGE_BYTES;                                  \
        uint32_t sB = sb + STAGES * STAGE_BYTES + (stage) * STAGE_BYTES;           \
        int k0 = (chunk) * BK;                                                     \
        _Pragma("unroll") for (int t = 0; t < 4; t++) {                            \
            int rr = r + t * 32;                                                   \
            cp16(sA + SWZ((uint32_t)(rr * 128 + o16)),                             \
                 A + (size_t)(m0 + rr) * K + k0 + c4);                             \
        }                                                                          \
        _Pragma("unroll") for (int t = 0; t < 4; t++) {                            \
            int rr = r + t * 32;                                                   \
            cp16(sB + SWZ((uint32_t)(rr * 128 + o16)),                             \
                 Bm + (size_t)(n0 + rr) * K + k0 + c4);                            \
        }                                                                          \
        CP_COMMIT();                                                               \
    } while (0)

    LOAD_STAGE(0, 0);
    LOAD_STAGE(1, 1);

    const int nk = K / BK;
    for (int i = 0; i < nk; i++) {
        const int st = i % STAGES;
        if (i + 2 < nk) {
            asm volatile("cp.async.wait_group 1;" ::: "memory");
            __syncthreads();
            LOAD_STAGE(i + 2, (i + 2) % STAGES);
        } else {
            asm volatile("cp.async.wait_group 0;" ::: "memory");
            __syncthreads();
        }
        const uint32_t sA = sb + st * STAGE_BYTES;
        const uint32_t sB = sb + STAGES * STAGE_BYTES + st * STAGE_BYTES;
#pragma unroll
        for (int ks = 0; ks < 4; ks++) {
            uint32_t a[4][4], b[2][4];
#pragma unroll
            for (int mt = 0; mt < 4; mt++)
                ldsm4(a[mt], sA + SWZ(a_base[mt] + (uint32_t)(ks * 32)));
#pragma unroll
            for (int nh = 0; nh < 2; nh++)
                ldsm4(b[nh], sB + SWZ(b_base[nh] + (uint32_t)(ks * 32)));
#pragma unroll
            for (int mt = 0; mt < 4; mt++)
#pragma unroll
                for (int nt = 0; nt < 4; nt++)
                    mma_tf32(acc[mt][nt], a[mt], b[nt >> 1][nt & 1], b[nt >> 1][(nt & 1) + 2]);
        }
    }
#undef LOAD_STAGE

    // Epilogue: direct float2 stores
    const int mrow = lane >> 2;
    const int mcol = (lane & 3) << 1;
#pragma unroll
    for (int mt = 0; mt < 4; mt++) {
#pragma unroll
        for (int nt = 0; nt < 4; nt++) {
            int row = m0 + warp_m * 64 + mt * 16 + mrow;
            int col = n0 + warp_n * 32 + nt * 8 + mcol;
            float2 v0 = make_float2(acc[mt][nt][0], acc[mt][nt][1]);
            float2 v1 = make_float2(acc[mt][nt][2], acc[mt][nt][3]);
            if (ROUND) {
                v0.x = rna_tf32(v0.x); v0.y = rna_tf32(v0.y);
                v1.x = rna_tf32(v1.x); v1.y = rna_tf32(v1.y);
            }
            *(float2*)&C[(size_t)row * ldc + col] = v0;
            *(float2*)&C[(size_t)(row + 8) * ldc + col] = v1;
        }
    }
}

// ---------------------------------------------------------------------------
// Transpose x[B,C,T,N] -> feat[(b*T+t)*N+n, c], RNA-rounded to tf32
// ---------------------------------------------------------------------------
__global__ void transpose_x(const float* __restrict__ x) {
    __shared__ float tile[32][33];
    const int b = blockIdx.z;
    const int c0 = blockIdx.y * 32;
    const int tn0 = blockIdx.x * 32;
    const int tx = threadIdx.x, ty = threadIdx.y;
    const float* xp = x + ((size_t)b * C_ + c0) * TN_ + tn0;
#pragma unroll
    for (int i = 0; i < 32; i += 8)
        tile[ty + i][tx] = xp[(size_t)(ty + i) * TN_ + tx];
    __syncthreads();
    float* fp = g_feat + ((size_t)b * TN_ + tn0) * NF_ + c0;
#pragma unroll
    for (int i = 0; i < 32; i += 8)
        fp[(size_t)(ty + i) * NF_ + tx] = rna_tf32(tile[tx][ty + i]);
}

// w_gcn [K,N] -> g_BigB rows 1024..2047 ([N,K]), rounded
__global__ void transpose_wg(const float* __restrict__ w) {
    __shared__ float tile[32][33];
    const int k0 = blockIdx.y * 32;
    const int n0 = blockIdx.x * 32;
    const int tx = threadIdx.x, ty = threadIdx.y;
#pragma unroll
    for (int i = 0; i < 32; i += 8)
        tile[ty + i][tx] = w[(size_t)(k0 + ty + i) * NF_ + n0 + tx];
    __syncthreads();
    float* dst = g_BigB + (size_t)NF_ * NF_;
#pragma unroll
    for (int i = 0; i < 32; i += 8)
        dst[(size_t)(n0 + ty + i) * NF_ + k0 + tx] = rna_tf32(tile[tx][ty + i]);
}

__global__ void round_copy(const float4* __restrict__ in, float4* __restrict__ out) {
    const int i = blockIdx.x * blockDim.x + threadIdx.x;
    float4 v = in[i];
    v.x = rna_tf32(v.x); v.y = rna_tf32(v.y);
    v.z = rna_tf32(v.z); v.w = rna_tf32(v.w);
    out[i] = v;
}

// ---------------------------------------------------------------------------
// Bias cross-term vectors (exact fp32) — warp-per-column, coalesced
// ---------------------------------------------------------------------------
__global__ void bias_vecs(const float* __restrict__ wt, const float* __restrict__ bt,
                          const float* __restrict__ wp, const float* __restrict__ bp) {
    const int lane = threadIdx.x & 31;
    const int warp = threadIdx.x >> 5;
    const int c = blockIdx.x * 8 + warp;          // 128 blocks x 8 warps = 1024 cols

    const float* wtr = wt + (size_t)c * NF_;
    const float* wpr = wp + (size_t)c * NF_;
    float a = 0.f, b2 = 0.f;
#pragma unroll
    for (int i = 0; i < 32; i++) {
        const int k = lane + 32 * i;
        a  += wtr[k] * bp[k];
        b2 += wpr[k] * bt[k];
    }
#pragma unroll
    for (int o = 16; o > 0; o >>= 1) {
        a  += __shfl_xor_sync(0xffffffffu, a, o);
        b2 += __shfl_xor_sync(0xffffffffu, b2, o);
    }
    if (lane == 0) { g_vtp[c] = a; g_vpt[c] = b2; }

    if (blockIdx.x == 0 && warp == 0) {
        float s = 0.f;
#pragma unroll
        for (int i = 0; i < 32; i++) {
            const int k = lane + 32 * i;
            s += bt[k] * bp[k];
        }
#pragma unroll
        for (int o = 16; o > 0; o >>= 1) s += __shfl_xor_sync(0xffffffffu, s, o);
        if (lane == 0) g_bb[0] = s;
    }
}

// ---------------------------------------------------------------------------
__device__ __forceinline__ float blockSum512(float v, float* red) {
    const int lane = threadIdx.x & 31, warp = threadIdx.x >> 5;
#pragma unroll
    for (int o = 16; o > 0; o >>= 1) v += __shfl_xor_sync(0xffffffffu, v, o);
    if (lane == 0) red[warp] = v;
    __syncthreads();
    if (threadIdx.x == 0) {
        float s = 0.f;
        for (int i = 0; i < 16; i++) s += red[i];
        red[16] = s;
    }
    __syncthreads();
    float r = red[16];
    __syncthreads();
    return r;
}

__global__ void __launch_bounds__(512) frame_kernel(const float* __restrict__ Abox,
                                                    const float* __restrict__ ln_w,
                                                    const float* __restrict__ ln_b,
                                                    float* __restrict__ out,
                                                    float* __restrict__ rg_out) {
    const int f = blockIdx.x;
    const int tid = threadIdx.x;
    const int lane = tid & 31, warp = tid >> 5;

    __shared__ float px[12], py[12], sqs[12];
    __shared__ float s_u[12], s_v[12];
    __shared__ float s_rg[12][12];
    __shared__ float red[17];

    if (tid < 12) {
        const float* bx = Abox + ((size_t)f * 12 + tid) * 4;
        float cx = (bx[0] + bx[2]) * 0.5f;
        float cy = (bx[1] + bx[3]) * 0.5f;
        px[tid] = cx; py[tid] = cy; sqs[tid] = cx * cx + cy * cy;
    }

    if (warp < 12) {
        const float* frow = g_feat + ((size_t)f * 12 + warp) * NF_;
        float ua = 0.f, va = 0.f;
#pragma unroll
        for (int k = 0; k < 32; k++) {
            float fv = frow[lane + 32 * k];
            ua += fv * g_vtp[lane + 32 * k];
            va += fv * g_vpt[lane + 32 * k];
        }
#pragma unroll
        for (int o = 16; o > 0; o >>= 1) {
            ua += __shfl_xor_sync(0xffffffffu, ua, o);
            va += __shfl_xor_sync(0xffffffffu, va, o);
        }
        if (lane == 0) { s_u[warp] = ua; s_v[warp] = va; }
    }
    __syncthreads();

    if (warp < 12) {
        const int n = warp;
        const float* tMrow = g_TG + ((size_t)f * 12 + n) * NB_;
        float tr[32];
#pragma unroll
        for (int k = 0; k < 32; k++) tr[k] = tMrow[lane + 32 * k];
        float lg[12];
#pragma unroll
        for (int m = 0; m < 12; m++) {
            const float* fm = g_feat + ((size_t)f * 12 + m) * NF_;
            float a = 0.f;
#pragma unroll
            for (int k = 0; k < 32; k++) a += tr[k] * fm[lane + 32 * k];
#pragma unroll
            for (int o = 16; o > 0; o >>= 1) a += __shfl_xor_sync(0xffffffffu, a, o);
            lg[m] = a;
        }
        if (lane == 0) {
            const float bb = g_bb[0];
            const float scale = 0.03125f;
            float e[12];
            bool msk[12];
            float mx = -INFINITY;
#pragma unroll
            for (int m = 0; m < 12; m++) {
                float d2 = sqs[n] - 2.f * (px[n] * px[m] + py[n] * py[m]) + sqs[m];
                d2 = fmaxf(d2, 0.f);
                float dist = sqrtf(d2);
                msk[m] = (dist > 0.4f);
                float v = (lg[m] + s_u[n] + s_v[m] + bb) * scale;
                e[m] = v;
                if (!msk[m]) mx = fmaxf(mx, v);
            }
            float se = 0.f;
#pragma unroll
            for (int m = 0; m < 12; m++) {
                float ev = msk[m] ? 0.f : expf(e[m] - mx);
                e[m] = ev;
                se += ev;
            }
            float inv = 1.f / se;
#pragma unroll
            for (int m = 0; m < 12; m++) {
                float r = e[m] * inv;
                s_rg[n][m] = r;
                if (rg_out) rg_out[((size_t)f * 12 + n) * 12 + m] = r;
            }
        }
    }
    __syncthreads();

    float aggv[2][12];
#pragma unroll
    for (int cc = 0; cc < 2; cc++) {
        const int c = tid + cc * 512;
        float g[12];
#pragma unroll
        for (int m = 0; m < 12; m++)
            g[m] = g_TG[((size_t)f * 12 + m) * NB_ + NF_ + c];
#pragma unroll
        for (int n = 0; n < 12; n++) {
            float a = 0.f;
#pragma unroll
            for (int m = 0; m < 12; m++) a += s_rg[n][m] * g[m];
            aggv[cc][n] = a;
        }
    }
    float lsum = 0.f;
#pragma unroll
    for (int cc = 0; cc < 2; cc++)
#pragma unroll
        for (int n = 0; n < 12; n++) lsum += aggv[cc][n];
    const float mu = blockSum512(lsum, red) * (1.f / 12288.f);

    float lsq = 0.f;
#pragma unroll
    for (int cc = 0; cc < 2; cc++)
#pragma unroll
        for (int n = 0; n < 12; n++) {
            float d = aggv[cc][n] - mu;
            lsq += d * d;
        }
    const float var = blockSum512(lsq, red) * (1.f / 12288.f);
    const float rstd = rsqrtf(var + 1e-5f);

#pragma unroll
    for (int cc = 0; cc < 2; cc++) {
        const int c = tid + cc * 512;
#pragma unroll
        for (int n = 0; n < 12; n++) {
            float y = (aggv[cc][n] - mu) * rstd * ln_w[n * NF_ + c] + ln_b[n * NF_ + c];
            out[((size_t)f * 12 + n) * NF_ + c] = fmaxf(y, 0.f);
        }
    }
}

// ---------------------------------------------------------------------------
extern "C" void kernel_launch(void* const* d_in, const int* in_sizes, int n_in,
                              void* d_out, int out_size) {
    const float* x  = (const float*)d_in[0];
    const float* A  = (const float*)d_in[1];
    const float* wt = (const float*)d_in[2];
    const float* bt = (const float*)d_in[3];
    const float* wp = (const float*)d_in[4];
    const float* bp = (const float*)d_in[5];
    const float* wg = (const float*)d_in[6];
    const float* lw = (const float*)d_in[7];
    const float* lb = (const float*)d_in[8];

    float* out = (float*)d_out;
    float* rg = (out_size >= (int)(ROWS_ * NF_ + BT_ * N_ * N_))
                    ? out + (size_t)ROWS_ * NF_
                    : nullptr;

    float *feat, *TG, *BigB, *wtr, *wpr;
    cudaGetSymbolAddress((void**)&feat, g_feat);
    cudaGetSymbolAddress((void**)&TG, g_TG);
    cudaGetSymbolAddress((void**)&BigB, g_BigB);
    cudaGetSymbolAddress((void**)&wtr, g_wtr);
    cudaGetSymbolAddress((void**)&wpr, g_wpr);

    cudaFuncSetAttribute(mma_gemm<true>,
                         cudaFuncAttributeMaxDynamicSharedMemorySize, GEMM_SMEM);
    cudaFuncSetAttribute(mma_gemm<false>,
                         cudaFuncAttributeMaxDynamicSharedMemorySize, GEMM_SMEM);

    // Order chosen so BOTH launch #4 and #6 are mma_gemm (ncu lands on one)
    round_copy<<<1024, 256>>>((const float4*)wt, (float4*)wtr);              // 1
    round_copy<<<1024, 256>>>((const float4*)wp, (float4*)wpr);              // 2
    transpose_wg<<<dim3(32, 32), dim3(32, 8)>>>(wg);                         // 3
    // MwT[n,k] = sum_r wphi[n,r]*wtheta[k,r]  -> BigB rows 0..1023 (rounded)
    mma_gemm<true><<<dim3(NF_ / BN, NF_ / BM), 256, GEMM_SMEM>>>(            // 4
        wpr, wtr, BigB, NF_, NF_);
    transpose_x<<<dim3(TN_ / 32, C_ / 32, B_), dim3(32, 8)>>>(x);            // 5
    // [tM | G] = feat @ [MwT | wg^T]^T   (fused, N = 2048)
    mma_gemm<false><<<dim3(NB_ / BN, ROWS_ / BM), 256, GEMM_SMEM>>>(         // 6
        feat, BigB, TG, NF_, NB_);

    bias_vecs<<<128, 256>>>(wt, bt, wp, bp);                                 // 7
    frame_kernel<<<BT_, 512>>>(A, lw, lb, out, rg);                          // 8
}

// round 7
// speedup vs baseline: 1.5461x; 1.0416x over previous
#include <cuda_runtime.h>
#include <math.h>
#include <stdint.h>

// Problem constants
#define B_    16
#define C_    1024
#define T_    64
#define N_    12
#define BT_   (B_ * T_)       // 1024 frames
#define NF_   1024
#define ROWS_ (BT_ * N_)      // 12288
#define TN_   (T_ * N_)       // 768
#define NB_   2048            // fused B rows: [MwT | wg^T]

// Scratch (static device globals)
__device__ float g_feat[ROWS_ * NF_];   // feat, RNA-rounded to tf32
__device__ float g_TG[ROWS_ * NB_];     // [tM | G] fused output
__device__ float g_BigB[NB_ * NF_];     // rows 0-1023: MwT, rows 1024-2047: wg^T
__device__ float g_wtr[NF_ * NF_];      // Wtheta rounded
__device__ float g_wpr[NF_ * NF_];      // Wphi rounded
__device__ float g_vtp[NF_];
__device__ float g_vpt[NF_];
__device__ float g_bb[1];

// ---------------------------------------------------------------------------
// Helpers (baseline PTX only — no arch-'a' gated instructions)
// ---------------------------------------------------------------------------
__device__ __forceinline__ float rna_tf32(float x) {
    float r;
    asm("cvt.rna.tf32.f32 %0, %1;" : "=f"(r) : "f"(x));
    return r;
}
__device__ __forceinline__ uint32_t smem_u32(const void* p) {
    uint32_t a;
    asm("{ .reg .u64 t; cvta.to.shared.u64 t, %1; cvt.u32.u64 %0, t; }" : "=r"(a) : "l"(p));
    return a;
}
__device__ __forceinline__ void cp16(uint32_t s, const void* g) {
    asm volatile("cp.async.cg.shared.global [%0], [%1], 16;" :: "r"(s), "l"(g) : "memory");
}
#define CP_COMMIT() asm volatile("cp.async.commit_group;" ::: "memory")
#define SWZ(x) ((x) ^ (((x) >> 3) & 0x70))

__device__ __forceinline__ void ldsm4(uint32_t* r, uint32_t addr) {
    asm volatile("ldmatrix.sync.aligned.m8n8.x4.shared.b16 {%0,%1,%2,%3}, [%4];"
                 : "=r"(r[0]), "=r"(r[1]), "=r"(r[2]), "=r"(r[3]) : "r"(addr));
}
__device__ __forceinline__ void mma_tf32(float* c, const uint32_t* a, uint32_t b0, uint32_t b1) {
    asm volatile("mma.sync.aligned.m16n8k8.row.col.f32.tf32.tf32.f32 "
                 "{%0,%1,%2,%3}, {%4,%5,%6,%7}, {%8,%9}, {%0,%1,%2,%3};"
                 : "+f"(c[0]), "+f"(c[1]), "+f"(c[2]), "+f"(c[3])
                 : "r"(a[0]), "r"(a[1]), "r"(a[2]), "r"(a[3]), "r"(b0), "r"(b1));
}

// ---------------------------------------------------------------------------
// Tensor-core tf32 GEMM: C[m,n] = sum_k A[m,k]*Bm[n,k]; A[M,K], Bm[N,K] row-major.
// Block BMTx128, K-chunk 32, 3-stage cp.async, 8 warps, 2 CTA/SM.
// ---------------------------------------------------------------------------
#define BN 128
#define BK 32
#define STAGES 3
#define B_STAGE 16384

template <int BMT, bool ROUND>
__global__ void __launch_bounds__(256, 2) mma_gemm(const float* __restrict__ A,
                                                   const float* __restrict__ Bm,
                                                   float* __restrict__ C,
                                                   int K, int ldc) {
    constexpr int MT = BMT / 32;           // A fragment tiles per warp (rows/16)
    constexpr int ASTAGE = BMT * 128;      // bytes per A stage
    extern __shared__ char smem[];
    const uint32_t sb = smem_u32(smem);
    const int tid = threadIdx.x, lane = tid & 31, wid = tid >> 5;
    const int m0 = blockIdx.y * BMT, n0 = blockIdx.x * BN;
    const int warp_m = wid & 1, warp_n = wid >> 1;

    // cp.async tiling: 8 threads x 16B per 128B row, 32 rows per pass
    const int r = tid >> 3;
    const int o16 = (tid & 7) << 4;
    const int c4 = (tid & 7) << 2;

    float acc[MT][4][4];
#pragma unroll
    for (int i = 0; i < MT; i++)
#pragma unroll
        for (int j = 0; j < 4; j++)
#pragma unroll
            for (int k = 0; k < 4; k++) acc[i][j][k] = 0.f;

    // ldmatrix per-lane UNSWIZZLED base offsets (swizzle applied per k-step;
    // base has bits 5-6 clear so base + ks*32 never carries pre-swizzle)
    const int lrow = lane & 15;
    const int lcol = (lane >> 4) << 4;
    uint32_t a_base[MT], b_base[2];
#pragma unroll
    for (int mt = 0; mt < MT; mt++)
        a_base[mt] = (uint32_t)((warp_m * (BMT / 2) + mt * 16 + lrow) * 128 + lcol);
#pragma unroll
    for (int nh = 0; nh < 2; nh++)
        b_base[nh] = (uint32_t)((warp_n * 32 + nh * 16 + lrow) * 128 + lcol);

#define LOAD_STAGE(chunk, stage)                                                   \
    do {                                                                           \
        uint32_t sA = sb + (stage) * ASTAGE;                                       \
        uint32_t sB = sb + STAGES * ASTAGE + (stage) * B_STAGE;                    \
        int k0 = (chunk) * BK;                                                     \
        _Pragma("unroll") for (int t = 0; t < BMT / 32; t++) {                     \
            int rr = r + t * 32;                                                   \
            cp16(sA + SWZ((uint32_t)(rr * 128 + o16)),                             \
                 A + (size_t)(m0 + rr) * K + k0 + c4);                             \
        }                                                                          \
        _Pragma("unroll") for (int t = 0; t < 4; t++) {                            \
            int rr = r + t * 32;                                                   \
            cp16(sB + SWZ((uint32_t)(rr * 128 + o16)),                             \
                 Bm + (size_t)(n0 + rr) * K + k0 + c4);                            \
        }                                                                          \
        CP_COMMIT();                                                               \
    } while (0)

    LOAD_STAGE(0, 0);
    LOAD_STAGE(1, 1);

    const int nk = K / BK;
    for (int i = 0; i < nk; i++) {
        const int st = i % STAGES;
        if (i + 2 < nk) {
            asm volatile("cp.async.wait_group 1;" ::: "memory");
            __syncthreads();
            LOAD_STAGE(i + 2, (i + 2) % STAGES);
        } else {
            asm volatile("cp.async.wait_group 0;" ::: "memory");
            __syncthreads();
        }
        const uint32_t sA = sb + st * ASTAGE;
        const uint32_t sB = sb + STAGES * ASTAGE + st * B_STAGE;
#pragma unroll
        for (int ks = 0; ks < 4; ks++) {
            uint32_t a[MT][4], b[2][4];
#pragma unroll
            for (int nh = 0; nh < 2; nh++)
                ldsm4(b[nh], sB + SWZ(b_base[nh] + (uint32_t)(ks * 32)));
#pragma unroll
            for (int mt = 0; mt < MT; mt++)
                ldsm4(a[mt], sA + SWZ(a_base[mt] + (uint32_t)(ks * 32)));
#pragma unroll
            for (int mt = 0; mt < MT; mt++)
#pragma unroll
                for (int nt = 0; nt < 4; nt++)
                    mma_tf32(acc[mt][nt], a[mt], b[nt >> 1][nt & 1], b[nt >> 1][(nt & 1) + 2]);
        }
    }
#undef LOAD_STAGE

    // Epilogue: direct float2 stores
    const int mrow = lane >> 2;
    const int mcol = (lane & 3) << 1;
#pragma unroll
    for (int mt = 0; mt < MT; mt++) {
#pragma unroll
        for (int nt = 0; nt < 4; nt++) {
            int row = m0 + warp_m * (BMT / 2) + mt * 16 + mrow;
            int col = n0 + warp_n * 32 + nt * 8 + mcol;
            float2 v0 = make_float2(acc[mt][nt][0], acc[mt][nt][1]);
            float2 v1 = make_float2(acc[mt][nt][2], acc[mt][nt][3]);
            if (ROUND) {
                v0.x = rna_tf32(v0.x); v0.y = rna_tf32(v0.y);
                v1.x = rna_tf32(v1.x); v1.y = rna_tf32(v1.y);
            }
            *(float2*)&C[(size_t)row * ldc + col] = v0;
            *(float2*)&C[(size_t)(row + 8) * ldc + col] = v1;
        }
    }
}

// ---------------------------------------------------------------------------
// Fused weight prep: blocks 0-1023 round wt, 1024-2047 round wp,
// 2048-3071 transpose+round wg into g_BigB rows 1024..2047.
// ---------------------------------------------------------------------------
__global__ void prep_w(const float* __restrict__ wt, const float* __restrict__ wp,
                       const float* __restrict__ wg) {
    const int bi = blockIdx.x;
    const int tid = threadIdx.x;
    if (bi < 2048) {
        const float4* in = (bi < 1024) ? (const float4*)wt : (const float4*)wp;
        float4* outp = (bi < 1024) ? (float4*)g_wtr : (float4*)g_wpr;
        const int i = (bi & 1023) * 256 + tid;
        float4 v = in[i];
        v.x = rna_tf32(v.x); v.y = rna_tf32(v.y);
        v.z = rna_tf32(v.z); v.w = rna_tf32(v.w);
        outp[i] = v;
    } else {
        __shared__ float tile[32][33];
        const int bb = bi - 2048;
        const int k0 = (bb >> 5) * 32;
        const int n0 = (bb & 31) * 32;
        const int tx = tid & 31, ty = tid >> 5;  // 32 x 8
#pragma unroll
        for (int i = 0; i < 32; i += 8)
            tile[ty + i][tx] = wg[(size_t)(k0 + ty + i) * NF_ + n0 + tx];
        __syncthreads();
        float* dst = g_BigB + (size_t)NF_ * NF_;
#pragma unroll
        for (int i = 0; i < 32; i += 8)
            dst[(size_t)(n0 + ty + i) * NF_ + k0 + tx] = rna_tf32(tile[tx][ty + i]);
    }
}

// ---------------------------------------------------------------------------
// Transpose x[B,C,T,N] -> feat[(b*T+t)*N+n, c], RNA-rounded to tf32
// ---------------------------------------------------------------------------
__global__ void transpose_x(const float* __restrict__ x) {
    __shared__ float tile[32][33];
    const int b = blockIdx.z;
    const int c0 = blockIdx.y * 32;
    const int tn0 = blockIdx.x * 32;
    const int tx = threadIdx.x, ty = threadIdx.y;
    const float* xp = x + ((size_t)b * C_ + c0) * TN_ + tn0;
#pragma unroll
    for (int i = 0; i < 32; i += 8)
        tile[ty + i][tx] = xp[(size_t)(ty + i) * TN_ + tx];
    __syncthreads();
    float* fp = g_feat + ((size_t)b * TN_ + tn0) * NF_ + c0;
#pragma unroll
    for (int i = 0; i < 32; i += 8)
        fp[(size_t)(ty + i) * NF_ + tx] = rna_tf32(tile[tx][ty + i]);
}

// ---------------------------------------------------------------------------
// Bias cross-term vectors (exact fp32) — warp-per-column, coalesced
// ---------------------------------------------------------------------------
__global__ void bias_vecs(const float* __restrict__ wt, const float* __restrict__ bt,
                          const float* __restrict__ wp, const float* __restrict__ bp) {
    const int lane = threadIdx.x & 31;
    const int warp = threadIdx.x >> 5;
    const int c = blockIdx.x * 8 + warp;

    const float* wtr = wt + (size_t)c * NF_;
    const float* wpr = wp + (size_t)c * NF_;
    float a = 0.f, b2 = 0.f;
#pragma unroll
    for (int i = 0; i < 32; i++) {
        const int k = lane + 32 * i;
        a  += wtr[k] * bp[k];
        b2 += wpr[k] * bt[k];
    }
#pragma unroll
    for (int o = 16; o > 0; o >>= 1) {
        a  += __shfl_xor_sync(0xffffffffu, a, o);
        b2 += __shfl_xor_sync(0xffffffffu, b2, o);
    }
    if (lane == 0) { g_vtp[c] = a; g_vpt[c] = b2; }

    if (blockIdx.x == 0 && warp == 0) {
        float s = 0.f;
#pragma unroll
        for (int i = 0; i < 32; i++) {
            const int k = lane + 32 * i;
            s += bt[k] * bp[k];
        }
#pragma unroll
        for (int o = 16; o > 0; o >>= 1) s += __shfl_xor_sync(0xffffffffu, s, o);
        if (lane == 0) g_bb[0] = s;
    }
}

// ---------------------------------------------------------------------------
__device__ __forceinline__ float blockSum512(float v, float* red) {
    const int lane = threadIdx.x & 31, warp = threadIdx.x >> 5;
#pragma unroll
    for (int o = 16; o > 0; o >>= 1) v += __shfl_xor_sync(0xffffffffu, v, o);
    if (lane == 0) red[warp] = v;
    __syncthreads();
    if (threadIdx.x == 0) {
        float s = 0.f;
        for (int i = 0; i < 16; i++) s += red[i];
        red[16] = s;
    }
    __syncthreads();
    float r = red[16];
    __syncthreads();
    return r;
}

__device__ __forceinline__ float dot4(float4 a, float4 b) {
    return a.x * b.x + a.y * b.y + a.z * b.z + a.w * b.w;
}

__global__ void __launch_bounds__(512) frame_kernel(const float* __restrict__ Abox,
                                                    const float* __restrict__ ln_w,
                                                    const float* __restrict__ ln_b,
                                                    float* __restrict__ out,
                                                    float* __restrict__ rg_out) {
    const int f = blockIdx.x;
    const int tid = threadIdx.x;
    const int lane = tid & 31, warp = tid >> 5;

    __shared__ float px[12], py[12], sqs[12];
    __shared__ float s_u[12], s_v[12];
    __shared__ float s_rg[12][12];
    __shared__ float red[17];

    if (tid < 12) {
        const float* bx = Abox + ((size_t)f * 12 + tid) * 4;
        float cx = (bx[0] + bx[2]) * 0.5f;
        float cy = (bx[1] + bx[3]) * 0.5f;
        px[tid] = cx; py[tid] = cy; sqs[tid] = cx * cx + cy * cy;
    }

    // phase 1: bias cross terms (float4 loads)
    if (warp < 12) {
        const float4* frow = (const float4*)(g_feat + ((size_t)f * 12 + warp) * NF_);
        const float4* vt4 = (const float4*)g_vtp;
        const float4* vp4 = (const float4*)g_vpt;
        float ua = 0.f, va = 0.f;
#pragma unroll
        for (int k = 0; k < 8; k++) {
            float4 fv = frow[lane + 32 * k];
            ua += dot4(fv, vt4[lane + 32 * k]);
            va += dot4(fv, vp4[lane + 32 * k]);
        }
#pragma unroll
        for (int o = 16; o > 0; o >>= 1) {
            ua += __shfl_xor_sync(0xffffffffu, ua, o);
            va += __shfl_xor_sync(0xffffffffu, va, o);
        }
        if (lane == 0) { s_u[warp] = ua; s_v[warp] = va; }
    }
    __syncthreads();

    // phase 2: logits row n = warp n (float4 loads); mask + softmax
    if (warp < 12) {
        const int n = warp;
        const float4* tM4 = (const float4*)(g_TG + ((size_t)f * 12 + n) * NB_);
        float4 tr[8];
#pragma unroll
        for (int k = 0; k < 8; k++) tr[k] = tM4[lane + 32 * k];
        float lg[12];
#pragma unroll
        for (int m = 0; m < 12; m++) {
            const float4* fm4 = (const float4*)(g_feat + ((size_t)f * 12 + m) * NF_);
            float a = 0.f;
#pragma unroll
            for (int k = 0; k < 8; k++) a += dot4(tr[k], fm4[lane + 32 * k]);
#pragma unroll
            for (int o = 16; o > 0; o >>= 1) a += __shfl_xor_sync(0xffffffffu, a, o);
            lg[m] = a;
        }
        if (lane == 0) {
            const float bb = g_bb[0];
            const float scale = 0.03125f;
            float e[12];
            bool msk[12];
            float mx = -INFINITY;
#pragma unroll
            for (int m = 0; m < 12; m++) {
                float d2 = sqs[n] - 2.f * (px[n] * px[m] + py[n] * py[m]) + sqs[m];
                d2 = fmaxf(d2, 0.f);
                float dist = sqrtf(d2);
                msk[m] = (dist > 0.4f);
                float v = (lg[m] + s_u[n] + s_v[m] + bb) * scale;
                e[m] = v;
                if (!msk[m]) mx = fmaxf(mx, v);
            }
            float se = 0.f;
#pragma unroll
            for (int m = 0; m < 12; m++) {
                float ev = msk[m] ? 0.f : expf(e[m] - mx);
                e[m] = ev;
                se += ev;
            }
            float inv = 1.f / se;
#pragma unroll
            for (int m = 0; m < 12; m++) {
                float r = e[m] * inv;
                s_rg[n][m] = r;
                if (rg_out) rg_out[((size_t)f * 12 + n) * 12 + m] = r;
            }
        }
    }
    __syncthreads();

    // phase 3: agg = rg @ G_f (float2: thread covers cols 2*tid, 2*tid+1)
    float2 aggv[12];
    {
        float2 gv[12];
#pragma unroll
        for (int m = 0; m < 12; m++)
            gv[m] = ((const float2*)(g_TG + ((size_t)f * 12 + m) * NB_ + NF_))[tid];
#pragma unroll
        for (int n = 0; n < 12; n++) {
            float ax = 0.f, ay = 0.f;
#pragma unroll
            for (int m = 0; m < 12; m++) {
                float w = s_rg[n][m];
                ax += w * gv[m].x;
                ay += w * gv[m].y;
            }
            aggv[n] = make_float2(ax, ay);
        }
    }
    float lsum = 0.f;
#pragma unroll
    for (int n = 0; n < 12; n++) lsum += aggv[n].x + aggv[n].y;
    const float mu = blockSum512(lsum, red) * (1.f / 12288.f);

    float lsq = 0.f;
#pragma unroll
    for (int n = 0; n < 12; n++) {
        float dx = aggv[n].x - mu, dy = aggv[n].y - mu;
        lsq += dx * dx + dy * dy;
    }
    const float var = blockSum512(lsq, red) * (1.f / 12288.f);
    const float rstd = rsqrtf(var + 1e-5f);

    const float2* lw2 = (const float2*)ln_w;
    const float2* lb2 = (const float2*)ln_b;
    float2* out2 = (float2*)out;
#pragma unroll
    for (int n = 0; n < 12; n++) {
        float2 w = lw2[n * 512 + tid];
        float2 b = lb2[n * 512 + tid];
        float yx = (aggv[n].x - mu) * rstd * w.x + b.x;
        float yy = (aggv[n].y - mu) * rstd * w.y + b.y;
        out2[((size_t)f * 12 + n) * 512 + tid] = make_float2(fmaxf(yx, 0.f), fmaxf(yy, 0.f));
    }
}

// ---------------------------------------------------------------------------
extern "C" void kernel_launch(void* const* d_in, const int* in_sizes, int n_in,
                              void* d_out, int out_size) {
    const float* x  = (const float*)d_in[0];
    const float* A  = (const float*)d_in[1];
    const float* wt = (const float*)d_in[2];
    const float* bt = (const float*)d_in[3];
    const float* wp = (const float*)d_in[4];
    const float* bp = (const float*)d_in[5];
    const float* wg = (const float*)d_in[6];
    const float* lw = (const float*)d_in[7];
    const float* lb = (const float*)d_in[8];

    float* out = (float*)d_out;
    float* rg = (out_size >= (int)(ROWS_ * NF_ + BT_ * N_ * N_))
                    ? out + (size_t)ROWS_ * NF_
                    : nullptr;

    float *feat, *TG, *BigB, *wtr, *wpr;
    cudaGetSymbolAddress((void**)&feat, g_feat);
    cudaGetSymbolAddress((void**)&TG, g_TG);
    cudaGetSymbolAddress((void**)&BigB, g_BigB);
    cudaGetSymbolAddress((void**)&wtr, g_wtr);
    cudaGetSymbolAddress((void**)&wpr, g_wpr);

    const int smem_small = STAGES * (64 * 128 + B_STAGE);    // 73728
    const int smem_big   = STAGES * (128 * 128 + B_STAGE);   // 98304
    cudaFuncSetAttribute(mma_gemm<64, true>,
                         cudaFuncAttributeMaxDynamicSharedMemorySize, smem_small);
    cudaFuncSetAttribute(mma_gemm<128, false>,
                         cudaFuncAttributeMaxDynamicSharedMemorySize, smem_big);

    // Launch order: big GEMM is launch #4 (ncu consistently profiles #4)
    prep_w<<<3072, 256>>>(wt, wp, wg);                                       // 1
    // MwT[n,k] = sum_r wphi[n,r]*wtheta[k,r] -> BigB rows 0..1023 (rounded)
    mma_gemm<64, true><<<dim3(NF_ / BN, NF_ / 64), 256, smem_small>>>(       // 2
        wpr, wtr, BigB, NF_, NF_);
    transpose_x<<<dim3(TN_ / 32, C_ / 32, B_), dim3(32, 8)>>>(x);            // 3
    // [tM | G] = feat @ [MwT | wg^T]^T   (fused, N = 2048)
    mma_gemm<128, false><<<dim3(NB_ / BN, ROWS_ / 128), 256, smem_big>>>(    // 4
        feat, BigB, TG, NF_, NB_);

    bias_vecs<<<128, 256>>>(wt, bt, wp, bp);                                 // 5
    frame_kernel<<<BT_, 512>>>(A, lw, lb, out, rg);                          // 6
}